// round 14
// baseline (speedup 1.0000x reference)
#include <cuda_runtime.h>

// ---------------- problem constants ----------------
#define KCLS 20
#define HH   480
#define WW   640
#define NPIX (HH * WW)           // 307200
#define NBATCH 4
#define FC   512
#define FH   30
#define FW   40
#define FHW  (FH * FW)           // 1200
#define NBOX 5
#define COUNT_THRESH 10000
#define XELEMS ((long long)(NBOX + 1) * NBATCH * FC * FHW)   // 14,745,600

// tiles for k_stats: 32x16 px, 600 blocks of 256 threads (float2 per thread)
#define TILX 20                  // 640/32
#define TILY 30                  // 480/16
#define NBLK (TILX * TILY)       // 600

// ---------------- device scratch (zero-init is neutral; tail resets) -----------
__device__ int      g_cnt[KCLS];
__device__ unsigned g_xlo[KCLS];        // coarse-x (x>>4) bits 0..31
__device__ unsigned g_xhi[KCLS];        // coarse-x bits 32..39
__device__ unsigned g_ym[KCLS];         // coarse-y (y>>4) bits 0..29
__device__ unsigned g_done;
__device__ int      g_node[NBOX][4];    // x0, y0, cw, ch

// ------- kernel 1: argmax(K=20) of batch 3 + stats + fused tail selection ------
__global__ void k_stats(const float* __restrict__ seg,
                        float* __restrict__ out, const float* __restrict__ pool,
                        int pool_n, int x_off) {
    __shared__ int      s_cnt[KCLS];
    __shared__ unsigned s_xlo[KCLS], s_xhi[KCLS], s_ym[KCLS];
    __shared__ int      s_last;
    int t = threadIdx.x;
    if (t < KCLS) { s_cnt[t] = 0; s_xlo[t] = 0; s_xhi[t] = 0; s_ym[t] = 0; }
    __syncthreads();

    // 32x16-pixel tile: spans exactly 2 coarse-x cells, 1 coarse-y cell
    int bt = blockIdx.x;
    int tilex = bt % TILX, tiley = bt / TILX;
    int tx2 = t & 15, ty2 = t >> 4;
    int x = tilex * 32 + tx2 * 2;           // even
    int y = tiley * 16 + ty2;

    const float2* base = (const float2*)(seg + (long long)3 * KCLS * NPIX);
    int poff = y * (WW / 2) + (x >> 1);

    float b0 = -1e30f, b1 = -1e30f;
    int   k0 = 0, k1 = 0;
#pragma unroll
    for (int k = 0; k < KCLS; k++) {
        float2 v = __ldg(base + k * (NPIX / 2) + poff);
        if (v.x > b0) { b0 = v.x; k0 = k; }
        if (v.y > b1) { b1 = v.y; k1 = k; }
    }

    int xc = x >> 4;                        // x and x+1 share the cell (x even)
    unsigned xbit  = (xc < 32) ? (1u << xc) : 0u;
    unsigned xbith = (xc < 32) ? 0u : (1u << (xc - 32));
    unsigned ybit  = 1u << (y >> 4);        // block-uniform

    int ks[2] = {k0, k1};
#pragma unroll
    for (int i = 0; i < 2; i++) {
        int k = ks[i];
        atomicAdd(&s_cnt[k], 1);
        // dedup ORs: racy read is benign (OR idempotent), skips ~all repeats
        if (xbit)  { if (!(s_xlo[k] & xbit))  atomicOr(&s_xlo[k], xbit); }
        else       { if (!(s_xhi[k] & xbith)) atomicOr(&s_xhi[k], xbith); }
        if (!(s_ym[k] & ybit)) atomicOr(&s_ym[k], ybit);
    }
    __syncthreads();

    if (t < KCLS && s_cnt[t] > 0) {
        atomicAdd(&g_cnt[t], s_cnt[t]);
        if (s_xlo[t]) atomicOr(&g_xlo[t], s_xlo[t]);
        if (s_xhi[t]) atomicOr(&g_xhi[t], s_xhi[t]);
        atomicOr(&g_ym[t], s_ym[t]);
    }
    __syncthreads();

    if (t == 0) {
        __threadfence();
        unsigned done = atomicAdd(&g_done, 1u);
        s_last = (done == gridDim.x - 1) ? 1 : 0;
    }
    __syncthreads();
    if (!s_last) return;

    // ---------- tail (last block): selection + pool/scalars + reset ----------
    if (t == 0) {
        int cand[KCLS], ccnt[KCLS];
        int m = 0, first_seen = -1;
        for (int k = 0; k < KCLS; k++) {
            int c = *(volatile int*)&g_cnt[k];
            if (c > 0) {
                if (first_seen < 0) first_seen = k;      // np.unique()[1:]
                else { cand[m] = k; ccnt[m] = c; m++; }
            }
        }
        bool used[KCLS];
        for (int i = 0; i < m; i++) used[i] = false;
        int selb[NBOX - 2];
        int selcnt = 0;
        for (int r = 0; r < m && selcnt < NBOX - 2; r++) {
            int best = -1;
            for (int j = 0; j < m; j++)
                if (!used[j] && (best < 0 || ccnt[j] > ccnt[best])) best = j;
            used[best] = true;
            if (ccnt[best] > COUNT_THRESH) selb[selcnt++] = cand[best];
        }
        for (int i = 0; i < selcnt; i++) {
            int k = selb[i];
            unsigned long long x64 =
                ((unsigned long long)(*(volatile unsigned*)&g_xhi[k]) << 32) |
                (*(volatile unsigned*)&g_xlo[k]);
            unsigned ym = *(volatile unsigned*)&g_ym[k];
            int x0 = __ffsll(x64) - 1;
            int x1 = 63 - __clzll(x64);
            int y0 = __ffs(ym) - 1;
            int y1 = 31 - __clz(ym);
            int cw = x1 - x0; if (cw < 1) cw = 1;
            int ch = y1 - y0; if (ch < 1) ch = 1;
            g_node[i][0] = x0; g_node[i][1] = y0;
            g_node[i][2] = cw; g_node[i][3] = ch;
        }
        const int bb[5][4] = {
            {FW / 4, FH / 4, 3 * FW / 4, 3 * FH / 4},
            {0, 0, FW / 3, FH},
            {0, 0, FW, FH / 3},
            {2 * FW / 3, 0, FW, FH},
            {0, 2 * FH / 3, FW, FH}};
        int need = NBOX - selcnt;
        for (int i = 0; i < need; i++) {
            int x0 = bb[i][0], y0 = bb[i][1];
            g_node[selcnt + i][0] = x0; g_node[selcnt + i][1] = y0;
            g_node[selcnt + i][2] = bb[i][2] - x0;
            g_node[selcnt + i][3] = bb[i][3] - y0;
        }
        if (x_off == pool_n + 2) {
            out[pool_n]     = (float)NBOX;     // 5
            out[pool_n + 1] = (float)NBATCH;   // 4
        }
        g_done = 0;
    }
    __syncthreads();                         // selection reads done before reset
    if (t < KCLS) {
        g_cnt[t] = 0; g_xlo[t] = 0; g_xhi[t] = 0; g_ym[t] = 0;
    }
    if (x_off >= pool_n)
        for (int i = t; i < pool_n; i += blockDim.x) out[i] = pool[i];
}

// ------- kernel 2: crop + bilinear via smem (8 channels/block), append feat ----
// grid (24, 64), block (20, 15). Divide-free clamped 2-D staging.
__global__ __launch_bounds__(300) void k_build(float* __restrict__ out_x,
                                               const float* __restrict__ feat) {
    __shared__ float sc[8][FH * FW];          // 38.4 KB
    int o  = blockIdx.x;
    int c0 = blockIdx.y << 3;                 // 8 channels
    int tx = threadIdx.x;                     // 0..19
    int ty = threadIdx.y;                     // 0..14
    int tid = ty * 20 + tx;                   // 0..299

    if (o >= 20) {                            // feat append, float2
        int n = o - 20;
        const float2* src = (const float2*)feat + ((n * FC + c0) * FHW >> 1);
        float2*       dst = (float2*)out_x + ((o * FC + c0) * FHW >> 1);
#pragma unroll
        for (int i = 0; i < 16; i++)          // 8ch * 600 float2 = 4800
            dst[tid + i * 300] = __ldg(src + tid + i * 300);
        return;
    }

    int n = o / NBOX;
    int b = o - n * NBOX;

    int x0 = g_node[b][0], y0 = g_node[b][1];
    int cw = g_node[b][2], ch = g_node[b][3];

    // ---- stage 8 channels: divide-free (ty+15j, tx+20k), clamped, coalesced ----
    {
        int sb = (n * FC + c0) * FHW + y0 * FW + x0;
        int che = ch - 1, cwe = cw - 1;
        int ry0c = min(ty, che)      * FW;
        int ry1c = min(ty + 15, che) * FW;
        int cx0c = min(tx, cwe);
        int cx1c = min(tx + 20, cwe);
#pragma unroll
        for (int cc = 0; cc < 8; cc++) {
            const float* src = feat + sb + cc * FHW;
            sc[cc][ty * FW + tx]              = __ldg(src + ry0c + cx0c);
            sc[cc][ty * FW + tx + 20]         = __ldg(src + ry0c + cx1c);
            sc[cc][(ty + 15) * FW + tx]       = __ldg(src + ry1c + cx0c);
            sc[cc][(ty + 15) * FW + tx + 20]  = __ldg(src + ry1c + cx1c);
        }
    }

    // ---- interp params in registers ----
    float sxs = (float)cw / (float)FW;
    float sys = (float)ch / (float)FH;
    int xa0, xb0, xa1, xb1; float fx0, fx1;
    {
        float s = ((float)(2 * tx) + 0.5f) * sxs - 0.5f;
        s = fminf(fmaxf(s, 0.0f), (float)(cw - 1));
        xa0 = (int)s; fx0 = s - (float)xa0; xb0 = min(xa0 + 1, cw - 1);
        s = ((float)(2 * tx + 1) + 0.5f) * sxs - 0.5f;
        s = fminf(fmaxf(s, 0.0f), (float)(cw - 1));
        xa1 = (int)s; fx1 = s - (float)xa1; xb1 = min(xa1 + 1, cw - 1);
    }
    int ry0[2], ry1[2]; float fyv[2];
#pragma unroll
    for (int hh = 0; hh < 2; hh++) {
        float s = ((float)(ty + hh * 15) + 0.5f) * sys - 0.5f;
        s = fminf(fmaxf(s, 0.0f), (float)(ch - 1));
        int ya = (int)s;
        fyv[hh] = s - (float)ya;
        ry0[hh] = ya * FW;
        ry1[hh] = min(ya + 1, ch - 1) * FW;
    }
    __syncthreads();

    int dst_base = (o * FC + c0) * FHW;
#pragma unroll
    for (int cc = 0; cc < 8; cc++) {
        const float* sp  = sc[cc];
        float*       dst = out_x + dst_base + cc * FHW;
#pragma unroll
        for (int hh = 0; hh < 2; hh++) {
            const float* r0 = sp + ry0[hh];
            const float* r1 = sp + ry1[hh];
            float fy  = fyv[hh];
            float ofy = 1.0f - fy;
            float t0 = (1.0f - fx0) * r0[xa0] + fx0 * r0[xb0];
            float u0 = (1.0f - fx0) * r1[xa0] + fx0 * r1[xb0];
            float t1 = (1.0f - fx1) * r0[xa1] + fx1 * r0[xb1];
            float u1 = (1.0f - fx1) * r1[xa1] + fx1 * r1[xb1];
            float2 pv;
            pv.x = ofy * t0 + fy * u0;
            pv.y = ofy * t1 + fy * u1;
            ((float2*)(dst + (ty + hh * 15) * FW))[tx] = pv;
        }
    }
}

// ---------------- launcher: 2 kernels ----------------
extern "C" void kernel_launch(void* const* d_in, const int* in_sizes, int n_in,
                              void* d_out, int out_size) {
    const float* seg  = (const float*)d_in[0];
    const float* feat = (const float*)d_in[1];
    const float* pool = (const float*)d_in[2];
    float* out = (float*)d_out;

    long long x_off_ll = (long long)out_size - XELEMS;
    if (x_off_ll < 0) x_off_ll = 0;
    int x_off = (int)x_off_ll;
    int pool_n = (n_in > 2) ? in_sizes[2] : 0;
    if (pool_n > x_off) pool_n = x_off;

    k_stats<<<NBLK, 256>>>(seg, out, pool, pool_n, x_off);
    dim3 grid((NBOX + 1) * NBATCH, FC / 8);     // (24, 64)
    dim3 blk(20, 15);
    k_build<<<grid, blk>>>(out + x_off, feat);
}

// round 15
// speedup vs baseline: 1.1212x; 1.1212x over previous
#include <cuda_runtime.h>

// ---------------- problem constants ----------------
#define KCLS 20
#define HH   480
#define WW   640
#define NPIX (HH * WW)           // 307200
#define NBATCH 4
#define FC   512
#define FH   30
#define FW   40
#define FHW  (FH * FW)           // 1200
#define NBOX 5
#define COUNT_THRESH 10000
#define XELEMS ((long long)(NBOX + 1) * NBATCH * FC * FHW)   // 14,745,600

// tiles for k_stats: 32x16 px, 600 blocks of 256 threads (float2 per thread)
#define TILX 20                  // 640/32
#define TILY 30                  // 480/16
#define NBLK (TILX * TILY)       // 600

#define DW 41                    // padded dup row stride (float2 units)

// ---------------- device scratch (zero-init is neutral; tail resets) -----------
__device__ int      g_cnt[KCLS];
__device__ unsigned g_xlo[KCLS];        // coarse-x (x>>4) bits 0..31
__device__ unsigned g_xhi[KCLS];        // coarse-x bits 32..39
__device__ unsigned g_ym[KCLS];         // coarse-y (y>>4) bits 0..29
__device__ unsigned g_done;
__device__ int      g_node[NBOX][4];    // x0, y0, cw, ch

// ------- kernel 1: argmax(K=20) of batch 3 + stats + fused tail selection ------
__global__ void k_stats(const float* __restrict__ seg,
                        float* __restrict__ out, const float* __restrict__ pool,
                        int pool_n, int x_off) {
    __shared__ int      s_cnt[KCLS];
    __shared__ unsigned s_xlo[KCLS], s_xhi[KCLS], s_ym[KCLS];
    __shared__ int      s_last;
    int t = threadIdx.x;
    if (t < KCLS) { s_cnt[t] = 0; s_xlo[t] = 0; s_xhi[t] = 0; s_ym[t] = 0; }
    __syncthreads();

    // 32x16-pixel tile: spans exactly 2 coarse-x cells, 1 coarse-y cell
    int bt = blockIdx.x;
    int tilex = bt % TILX, tiley = bt / TILX;
    int tx2 = t & 15, ty2 = t >> 4;
    int x = tilex * 32 + tx2 * 2;           // even
    int y = tiley * 16 + ty2;

    const float2* base = (const float2*)(seg + (long long)3 * KCLS * NPIX);
    int poff = y * (WW / 2) + (x >> 1);

    float b0 = -1e30f, b1 = -1e30f;
    int   k0 = 0, k1 = 0;
#pragma unroll
    for (int k = 0; k < KCLS; k++) {
        float2 v = __ldg(base + k * (NPIX / 2) + poff);
        if (v.x > b0) { b0 = v.x; k0 = k; }
        if (v.y > b1) { b1 = v.y; k1 = k; }
    }

    int xc = x >> 4;                        // x and x+1 share the cell (x even)
    unsigned xbit  = (xc < 32) ? (1u << xc) : 0u;
    unsigned xbith = (xc < 32) ? 0u : (1u << (xc - 32));
    unsigned ybit  = 1u << (y >> 4);        // block-uniform

    int ks[2] = {k0, k1};
#pragma unroll
    for (int i = 0; i < 2; i++) {
        int k = ks[i];
        atomicAdd(&s_cnt[k], 1);
        // dedup ORs: racy read is benign (OR idempotent), skips ~all repeats
        if (xbit)  { if (!(s_xlo[k] & xbit))  atomicOr(&s_xlo[k], xbit); }
        else       { if (!(s_xhi[k] & xbith)) atomicOr(&s_xhi[k], xbith); }
        if (!(s_ym[k] & ybit)) atomicOr(&s_ym[k], ybit);
    }
    __syncthreads();

    if (t < KCLS && s_cnt[t] > 0) {
        atomicAdd(&g_cnt[t], s_cnt[t]);
        if (s_xlo[t]) atomicOr(&g_xlo[t], s_xlo[t]);
        if (s_xhi[t]) atomicOr(&g_xhi[t], s_xhi[t]);
        atomicOr(&g_ym[t], s_ym[t]);
    }
    __syncthreads();

    if (t == 0) {
        __threadfence();
        unsigned done = atomicAdd(&g_done, 1u);
        s_last = (done == gridDim.x - 1) ? 1 : 0;
    }
    __syncthreads();
    if (!s_last) return;

    // ---------- tail (last block): selection + pool/scalars + reset ----------
    if (t == 0) {
        int cand[KCLS], ccnt[KCLS];
        int m = 0, first_seen = -1;
        for (int k = 0; k < KCLS; k++) {
            int c = *(volatile int*)&g_cnt[k];
            if (c > 0) {
                if (first_seen < 0) first_seen = k;      // np.unique()[1:]
                else { cand[m] = k; ccnt[m] = c; m++; }
            }
        }
        bool used[KCLS];
        for (int i = 0; i < m; i++) used[i] = false;
        int selb[NBOX - 2];
        int selcnt = 0;
        for (int r = 0; r < m && selcnt < NBOX - 2; r++) {
            int best = -1;
            for (int j = 0; j < m; j++)
                if (!used[j] && (best < 0 || ccnt[j] > ccnt[best])) best = j;
            used[best] = true;
            if (ccnt[best] > COUNT_THRESH) selb[selcnt++] = cand[best];
        }
        for (int i = 0; i < selcnt; i++) {
            int k = selb[i];
            unsigned long long x64 =
                ((unsigned long long)(*(volatile unsigned*)&g_xhi[k]) << 32) |
                (*(volatile unsigned*)&g_xlo[k]);
            unsigned ym = *(volatile unsigned*)&g_ym[k];
            int x0 = __ffsll(x64) - 1;
            int x1 = 63 - __clzll(x64);
            int y0 = __ffs(ym) - 1;
            int y1 = 31 - __clz(ym);
            int cw = x1 - x0; if (cw < 1) cw = 1;
            int ch = y1 - y0; if (ch < 1) ch = 1;
            g_node[i][0] = x0; g_node[i][1] = y0;
            g_node[i][2] = cw; g_node[i][3] = ch;
        }
        const int bb[5][4] = {
            {FW / 4, FH / 4, 3 * FW / 4, 3 * FH / 4},
            {0, 0, FW / 3, FH},
            {0, 0, FW, FH / 3},
            {2 * FW / 3, 0, FW, FH},
            {0, 2 * FH / 3, FW, FH}};
        int need = NBOX - selcnt;
        for (int i = 0; i < need; i++) {
            int x0 = bb[i][0], y0 = bb[i][1];
            g_node[selcnt + i][0] = x0; g_node[selcnt + i][1] = y0;
            g_node[selcnt + i][2] = bb[i][2] - x0;
            g_node[selcnt + i][3] = bb[i][3] - y0;
        }
        if (x_off == pool_n + 2) {
            out[pool_n]     = (float)NBOX;     // 5
            out[pool_n + 1] = (float)NBATCH;   // 4
        }
        g_done = 0;
    }
    __syncthreads();                         // selection reads done before reset
    if (t < KCLS) {
        g_cnt[t] = 0; g_xlo[t] = 0; g_xhi[t] = 0; g_ym[t] = 0;
    }
    if (x_off >= pool_n)
        for (int i = t; i < pool_n; i += blockDim.x) out[i] = pool[i];
}

// ------- kernel 2: fused per-(n, 2ch) block: dup-staged plane serves ALL 5 -----
// resize planes + feat copy. Horizontal tap pair = ONE LDS.64 from dup layout.
// grid (4, 256), block (20, 15).
__global__ __launch_bounds__(300) void k_build(float* __restrict__ out_x,
                                               const float* __restrict__ feat) {
    __shared__ float2 dup[2][FH * DW];        // 2ch x 30x41 float2 = 19.7 KB
    int n  = blockIdx.x;                      // 0..3
    int c0 = blockIdx.y << 1;                 // 2 channels
    int tx = threadIdx.x;                     // 0..19
    int ty = threadIdx.y;                     // 0..14
    int tid = ty * 20 + tx;

    const float* p0 = feat + (n * FC + c0) * FHW;

    // ---- stage dup (box-independent): dup[h][x] = (v[x], v[min(x+1,39)]) ----
#pragma unroll
    for (int cc = 0; cc < 2; cc++) {
        const float* src = p0 + cc * FHW;
#pragma unroll
        for (int jh = 0; jh < 2; jh++) {
#pragma unroll
            for (int jw = 0; jw < 2; jw++) {
                int h = ty + 15 * jh, w = tx + 20 * jw;
                float a  = __ldg(src + h * FW + w);
                float bq = __ldg(src + h * FW + min(w + 1, FW - 1));
                dup[cc][h * DW + w] = make_float2(a, bq);
            }
        }
    }

    // ---- feat-copy plane (20+n), overlapped before the sync ----
    {
        const float2* srcv = (const float2*)feat + ((n * FC + c0) * FHW >> 1);
        float2*       dstv = (float2*)out_x + (((20 + n) * FC + c0) * FHW >> 1);
#pragma unroll
        for (int i = 0; i < 4; i++)           // 2ch * 600 float2 = 1200
            dstv[tid + i * 300] = __ldg(srcv + tid + i * 300);
    }
    __syncthreads();

    // ---- 5 resize planes from the same dup ----
    for (int b = 0; b < NBOX; b++) {
        int x0 = g_node[b][0], y0 = g_node[b][1];
        int cw = g_node[b][2], ch = g_node[b][3];
        float sxs = (float)cw / (float)FW;
        float sys = (float)ch / (float)FH;

        // horizontal params for w = 2tx, 2tx+1 (global plane column)
        int gx0, gx1; float fx0, fx1;
        {
            float s = ((float)(2 * tx) + 0.5f) * sxs - 0.5f;
            s = fminf(fmaxf(s, 0.0f), (float)(cw - 1));
            int xa = (int)s; fx0 = s - (float)xa; gx0 = x0 + xa;
            s = ((float)(2 * tx + 1) + 0.5f) * sxs - 0.5f;
            s = fminf(fmaxf(s, 0.0f), (float)(cw - 1));
            xa = (int)s; fx1 = s - (float)xa; gx1 = x0 + xa;
        }
        // vertical params for h = ty, ty+15 (precomputed dup-row offsets)
        int ra[2], rb[2]; float fyv[2];
#pragma unroll
        for (int hh = 0; hh < 2; hh++) {
            float s = ((float)(ty + hh * 15) + 0.5f) * sys - 0.5f;
            s = fminf(fmaxf(s, 0.0f), (float)(ch - 1));
            int ya = (int)s;
            fyv[hh] = s - (float)ya;
            int r = y0 + ya;
            ra[hh] = r * DW;
            rb[hh] = min(r + 1, FH - 1) * DW;  // when fy==0 row is x0 anyway
        }

        int dst_base = ((n * NBOX + b) * FC + c0) * FHW;
#pragma unroll
        for (int cc = 0; cc < 2; cc++) {
            const float2* dp = dup[cc];
            float* dst = out_x + dst_base + cc * FHW;
#pragma unroll
            for (int hh = 0; hh < 2; hh++) {
                float2 a0 = dp[ra[hh] + gx0];   // (v[xa], v[xa+1]) row ya
                float2 b0 = dp[rb[hh] + gx0];   // row ya+1
                float2 a1 = dp[ra[hh] + gx1];
                float2 b1 = dp[rb[hh] + gx1];
                float fy = fyv[hh], ofy = 1.0f - fy;
                float t0 = (1.0f - fx0) * a0.x + fx0 * a0.y;
                float u0 = (1.0f - fx0) * b0.x + fx0 * b0.y;
                float t1 = (1.0f - fx1) * a1.x + fx1 * a1.y;
                float u1 = (1.0f - fx1) * b1.x + fx1 * b1.y;
                float2 pv;
                pv.x = ofy * t0 + fy * u0;
                pv.y = ofy * t1 + fy * u1;
                ((float2*)(dst + (ty + hh * 15) * FW))[tx] = pv;
            }
        }
    }
}

// ---------------- launcher: 2 kernels ----------------
extern "C" void kernel_launch(void* const* d_in, const int* in_sizes, int n_in,
                              void* d_out, int out_size) {
    const float* seg  = (const float*)d_in[0];
    const float* feat = (const float*)d_in[1];
    const float* pool = (const float*)d_in[2];
    float* out = (float*)d_out;

    long long x_off_ll = (long long)out_size - XELEMS;
    if (x_off_ll < 0) x_off_ll = 0;
    int x_off = (int)x_off_ll;
    int pool_n = (n_in > 2) ? in_sizes[2] : 0;
    if (pool_n > x_off) pool_n = x_off;

    k_stats<<<NBLK, 256>>>(seg, out, pool, pool_n, x_off);
    dim3 grid(NBATCH, FC / 2);                // (4, 256)
    dim3 blk(20, 15);
    k_build<<<grid, blk>>>(out + x_off, feat);
}